// round 4
// baseline (speedup 1.0000x reference)
#include <cuda_runtime.h>
#include <cstdint>

// ---------------------------------------------------------------------------
// STGN_LSTM reference has NO recurrence: h_prev/c_prev are never updated in
// the loop, so only t=4 (last step) matters and all h@W terms are zero.
// Effective math per batch row (x0,x1,dt = X[row, 4, 0..2]):
//   zi[n] = Wix[n,0]x0 + Wix[n,1]x1 + (Wih_b+Wix_b+bi)[n]
//   zT[n] = WTx[n,0]x0 + WTx[n,1]x1 + WTt[n]dt + (WTh_b+WTx_b+WTt_b+bT)[n]
//   h[n]  = tanh( sig(zi)*tanh( sig(zT)*dt ) )
//   out   = sigmoid( sum_n h[n]*cls_w[n] + cls_b )
// Pointwise, MUFU-bound. Thread-per-row; per-unit constants in smem float4
// tables (broadcast LDS).
// ---------------------------------------------------------------------------

static __device__ __forceinline__ float tanh_fast(float x) {
    float y; asm("tanh.approx.f32 %0, %1;" : "=f"(y) : "f"(x)); return y;
}
static __device__ __forceinline__ float sig_fast(float z) {
    return fmaf(0.5f, tanh_fast(0.5f * z), 0.5f);
}

__global__ void __launch_bounds__(256)
stgn_kernel(const float* __restrict__ X,
            const float* __restrict__ Wfh_b,
            const float* __restrict__ Wix, const float* __restrict__ Wix_b,
            const float* __restrict__ Wih_b, const float* __restrict__ bi,
            const float* __restrict__ WTx, const float* __restrict__ WTx_b,
            const float* __restrict__ WTh_b,
            const float* __restrict__ WTt, const float* __restrict__ WTt_b,
            const float* __restrict__ bT,
            const float* __restrict__ clsw, const float* __restrict__ clsb,
            float* __restrict__ out, int nrows) {
    __shared__ float4 AU[64];   // (Wix0, Wix1, biSum, WTt)
    __shared__ float4 AV[64];   // (WTx0, WTx1, bTSum, clsw)
    __shared__ float  cbS;

    const int tid = threadIdx.x;
    if (tid < 64) {
        const int n = tid;
        AU[n] = make_float4(Wix[2 * n], Wix[2 * n + 1],
                            Wih_b[n] + Wix_b[n] + bi[n], WTt[n]);
        AV[n] = make_float4(WTx[2 * n], WTx[2 * n + 1],
                            WTh_b[n] + WTx_b[n] + WTt_b[n] + bT[n], clsw[n]);
    }
    if (tid == 0) cbS = clsb[0];
    __syncthreads();

    const int row = blockIdx.x * 256 + tid;
    if (row >= nrows) return;

    // x at t=4: offsets 12,13,14 within the 15-float row
    const float* xr = X + (size_t)row * 15 + 12;
    const float x0 = xr[0];
    const float x1 = xr[1];
    const float dt = xr[2];

    float logit = cbS;

#pragma unroll 8
    for (int n = 0; n < 64; n++) {
        const float4 u = AU[n];
        const float4 v = AV[n];
        const float zi = fmaf(u.x, x0, fmaf(u.y, x1, u.z));
        const float zT = fmaf(v.x, x0, fmaf(v.y, x1, fmaf(u.w, dt, v.z)));
        const float ig = sig_fast(zi);
        const float Tg = sig_fast(zT);
        const float cc = ig * tanh_fast(Tg * dt);
        const float h  = tanh_fast(cc);
        logit = fmaf(h, v.w, logit);
    }

    // precise output sigmoid
    out[row] = __fdividef(1.0f, 1.0f + __expf(-logit));
}

extern "C" void kernel_launch(void* const* d_in, const int* in_sizes, int n_in,
                              void* d_out, int out_size) {
    const float* X      = (const float*)d_in[0];
    const float* Wfh_b  = (const float*)d_in[2];
    const float* Wix_w  = (const float*)d_in[8];
    const float* Wix_b  = (const float*)d_in[9];
    const float* Wih_b  = (const float*)d_in[7];
    const float* bi     = (const float*)d_in[10];
    const float* WTh_b  = (const float*)d_in[12];
    const float* WTx_w  = (const float*)d_in[13];
    const float* WTx_b  = (const float*)d_in[14];
    const float* WTt_w  = (const float*)d_in[15];
    const float* WTt_b  = (const float*)d_in[16];
    const float* bT     = (const float*)d_in[17];
    const float* cls_w  = (const float*)d_in[18];
    const float* cls_b  = (const float*)d_in[19];

    const int nrows = in_sizes[0] / 15;
    const int blocks = (nrows + 255) / 256;

    stgn_kernel<<<blocks, 256>>>(
        X, Wfh_b, Wix_w, Wix_b, Wih_b, bi,
        WTx_w, WTx_b, WTh_b, WTt_w, WTt_b, bT,
        cls_w, cls_b, (float*)d_out, nrows);
}